// round 12
// baseline (speedup 1.0000x reference)
#include <cuda_runtime.h>
#include <cuda_fp16.h>
#include <cstdint>

// ============================================================================
// MQA_22436909154690 on GB300 (sm_103 base PTX target -> HMMA mma.sync path).
//
// Math: softmax over singleton axis == 1, so
//   out[b,l] = tile(v[b,l], H),  v = x @ Wv^T + bv,  Wv = Wkv[HD:2HD, :]
// => one GEMM [16384 x 2048] @ [2048 x 128] + bias + broadcast-x16 epilogue.
//
// R12 = R11 split-K(2) with a FIXED rendezvous protocol. R11 deadlocked on
// graph replay: one counter served as both order and publish signal, leaving
// cnt=1 after each run. Now: g_cnt = ordering only (loser resets to 0),
// g_flag = publish handshake only (winner sets 1 after threadfence; loser
// spins, resets to 0). Both cells are 0 again after every run -> replay-safe.
// Loser only waits on a CTA that already passed the rendezvous -> no deadlock.
// ============================================================================

static constexpr int KDIM  = 2048;
static constexpr int MTILE = 64;
static constexpr int KC    = 64;
static constexpr int NCHH  = 16;                     // chunks per CTA (half K)

// SMEM (bytes). 72 halves/row padding -> conflict-free ldmatrix.
static constexpr int SA0 = 0;                        // A buf0: [64][72] half
static constexpr int SA1 = 9216;                     // A buf1
static constexpr int SB  = 18432;                    // B bufs: 3 x [128][72] half
static constexpr int SBSZ = 18432;
static constexpr int SMEM_TOTAL = SB + 3 * SBSZ;     // 73728 -> occ 2
static constexpr int V_STRIDE  = 132;                // epilogue overlay

// Pre-converted Wv in fp16, chunk-major: [chunk][n=128][k=64]
__device__ __align__(16) __half g_Wh[KDIM * 128];
// Split-K scratch: per-tile partial v (64x128 fp32), order counters, flags.
__device__ __align__(16) float g_part[256 * 64 * 128];   // 8 MB
__device__ int g_cnt[256];    // ordering;   returns to 0 after every run
__device__ int g_flag[256];   // publish bit; returns to 0 after every run

// ---------------------------------------------------------------------------
__device__ __forceinline__ uint32_t smem_u32(const void* p) {
    uint32_t a;
    asm("{ .reg .u64 t; cvta.to.shared.u64 t, %1; cvt.u32.u64 %0, t; }" : "=r"(a) : "l"(p));
    return a;
}
__device__ __forceinline__ void ldsm4(uint32_t* r, uint32_t addr) {
    asm volatile("ldmatrix.sync.aligned.m8n8.x4.shared.b16 {%0,%1,%2,%3}, [%4];"
                 : "=r"(r[0]), "=r"(r[1]), "=r"(r[2]), "=r"(r[3]) : "r"(addr));
}
__device__ __forceinline__ void hmma(float* d, const uint32_t* a, uint32_t b0, uint32_t b1) {
    asm volatile("mma.sync.aligned.m16n8k16.row.col.f32.f16.f16.f32 "
                 "{%0,%1,%2,%3}, {%4,%5,%6,%7}, {%8,%9}, {%0,%1,%2,%3};"
                 : "+f"(d[0]), "+f"(d[1]), "+f"(d[2]), "+f"(d[3])
                 : "r"(a[0]), "r"(a[1]), "r"(a[2]), "r"(a[3]), "r"(b0), "r"(b1));
}
template <int N>
__device__ __forceinline__ void cpwait() {
    asm volatile("cp.async.wait_group %0;" :: "n"(N) : "memory");
}
__device__ __forceinline__ void cpcommit() {
    asm volatile("cp.async.commit_group;" ::: "memory");
}
__device__ __forceinline__ void cpa16(uint32_t dst, const void* src) {
    asm volatile("cp.async.cg.shared.global [%0], [%1], 16;" :: "r"(dst), "l"(src) : "memory");
}
__device__ __forceinline__ uint32_t h2u(__half2 h) { return *reinterpret_cast<uint32_t*>(&h); }

// ---------------------------------------------------------------------------
// Pre-kernel: Wv = Wkv rows 128..255 -> fp16, chunk-major layout for cp.async.
// ---------------------------------------------------------------------------
__global__ void convert_w_kernel(const float* __restrict__ Wkv) {
    int idx = blockIdx.x * blockDim.x + threadIdx.x;  // 65536 units of 4 halves
    int h4 = idx << 2;
    int c  = h4 >> 13;
    int n  = (h4 >> 6) & 127;
    int k4 = h4 & 63;
    float4 w = *(const float4*)(Wkv + (size_t)(128 + n) * KDIM + c * KC + k4);
    __half2 p0 = __float22half2_rn(make_float2(w.x, w.y));
    __half2 p1 = __float22half2_rn(make_float2(w.z, w.w));
    *(uint2*)(g_Wh + h4) = make_uint2(h2u(p0), h2u(p1));
}

// ---------------------------------------------------------------------------
// 512 CTAs x 256 threads, occ 2 (2 waves). 8 warps as 2(M) x 4(N).
// ---------------------------------------------------------------------------
__global__ void __launch_bounds__(256, 2)
mqa_gemm_kernel(const float* __restrict__ x, const float* __restrict__ bkv,
                float* __restrict__ out) {
    extern __shared__ char smem[];
    const uint32_t sb = smem_u32(smem);
    const int tid    = threadIdx.x;
    const int wid    = tid >> 5;
    const int lane   = tid & 31;
    const int warp_m = wid >> 2;
    const int warp_n = wid & 3;
    const int tile   = blockIdx.x >> 1;
    const int kbase  = (blockIdx.x & 1) * NCHH;        // chunk offset for this half

    const float* xb = x + (size_t)tile * MTILE * KDIM;

    // ldmatrix offsets (within an A / B buffer)
    uint32_t aOff[2];
    #pragma unroll
    for (int mf = 0; mf < 2; ++mf)
        aOff[mf] = (((warp_m * 32 + mf * 16 + (lane & 15)) * 72) << 1) + ((lane >> 4) << 4);
    uint32_t bOff[2];
    #pragma unroll
    for (int g = 0; g < 2; ++g)
        bOff[g] = (((warp_n * 32 + g * 16 + (lane & 15)) * 72) << 1) + ((lane >> 4) << 4);

    float acc[2][4][4];
    #pragma unroll
    for (int mf = 0; mf < 2; ++mf)
        #pragma unroll
        for (int nf = 0; nf < 4; ++nf)
            #pragma unroll
            for (int r = 0; r < 4; ++r) acc[mf][nf][r] = 0.f;

    float4 xs[2][2];
    const int f8a = tid;
    const int f8b = tid + 256;

    auto ldx = [&](int ch) {
        const float* p0 = xb + (size_t)(f8a >> 3) * KDIM + ch * KC + ((f8a & 7) << 3);
        const float* p1 = xb + (size_t)(f8b >> 3) * KDIM + ch * KC + ((f8b & 7) << 3);
        xs[0][0] = __ldcs((const float4*)p0);
        xs[0][1] = __ldcs((const float4*)p0 + 1);
        xs[1][0] = __ldcs((const float4*)p1);
        xs[1][1] = __ldcs((const float4*)p1 + 1);
    };
    auto stx = [&](int buf) {
        uint32_t base = (buf ? SA1 : SA0);
        #pragma unroll
        for (int i = 0; i < 2; ++i) {
            int f8 = (i ? f8b : f8a);
            __half2 h0 = __float22half2_rn(make_float2(xs[i][0].x, xs[i][0].y));
            __half2 h1 = __float22half2_rn(make_float2(xs[i][0].z, xs[i][0].w));
            __half2 h2 = __float22half2_rn(make_float2(xs[i][1].x, xs[i][1].y));
            __half2 h3 = __float22half2_rn(make_float2(xs[i][1].z, xs[i][1].w));
            uint4 v = make_uint4(h2u(h0), h2u(h1), h2u(h2), h2u(h3));
            *(uint4*)(smem + base + (((f8 >> 3) * 72 + ((f8 & 7) << 3)) << 1)) = v;
        }
    };
    auto cpB = [&](int ch, int buf) {
        const __half* src = g_Wh + (size_t)ch * (128 * KC);
        uint32_t dbase = sb + SB + buf * SBSZ;
        #pragma unroll
        for (int j = 0; j < 4; ++j) {
            int idx = tid + j * 256;
            int n = idx >> 3, seg = idx & 7;
            cpa16(dbase + ((n * 72 + seg * 8) << 1), src + n * KC + seg * 8);
        }
        cpcommit();
    };
    auto mmaChunk = [&](int abuf, int bbuf) {
        uint32_t bA = sb + (abuf ? SA1 : SA0);
        uint32_t bB = sb + SB + bbuf * SBSZ;
        #pragma unroll
        for (int kk = 0; kk < 4; ++kk) {
            uint32_t a[2][4];
            ldsm4(a[0], bA + aOff[0] + kk * 32);
            ldsm4(a[1], bA + aOff[1] + kk * 32);
            uint32_t b[2][4];
            ldsm4(b[0], bB + bOff[0] + kk * 32);
            ldsm4(b[1], bB + bOff[1] + kk * 32);
            #pragma unroll
            for (int mf = 0; mf < 2; ++mf) {
                hmma(acc[mf][0], a[mf], b[0][0], b[0][2]);
                hmma(acc[mf][1], a[mf], b[0][1], b[0][3]);
                hmma(acc[mf][2], a[mf], b[1][0], b[1][2]);
                hmma(acc[mf][3], a[mf], b[1][1], b[1][3]);
            }
        }
    };

    // --- prologue ---
    cpB(kbase + 0, 0);
    cpB(kbase + 1, 1);
    ldx(kbase + 0);
    stx(0);
    ldx(kbase + 1);
    cpwait<1>();
    __syncthreads();

    // --- main loop: 16 chunks, one barrier each ---
    for (int it = 0; it < NCHH; ++it) {
        if (it + 1 < NCHH) stx((it + 1) & 1);
        if (it + 2 < NCHH) { ldx(kbase + it + 2); cpB(kbase + it + 2, (it + 2) % 3); }
        mmaChunk(it & 1, it % 3);
        if (it + 2 < NCHH) cpwait<1>();
        else               cpwait<0>();
        __syncthreads();
    }

    // --- split-K pair rendezvous (ordering via g_cnt, publish via g_flag) ---
    const int r0 = warp_m * 32 + (lane >> 2);
    const int c0 = warp_n * 32 + (lane & 3) * 2;
    float* gp = g_part + (size_t)tile * (64 * 128);

    int* flag = (int*)smem;            // reuse smem (mainloop done)
    if (tid == 0) *flag = atomicAdd(&g_cnt[tile], 1);
    __syncthreads();
    const int order = *flag;
    __syncthreads();

    if (order == 0) {
        // First finisher: publish partial, raise flag, exit (frees the slot).
        #pragma unroll
        for (int mf = 0; mf < 2; ++mf) {
            #pragma unroll
            for (int nf = 0; nf < 4; ++nf) {
                int r = r0 + mf * 16;
                int c = c0 + nf * 8;
                *(float2*)(gp + (size_t)r * 128 + c) =
                    make_float2(acc[mf][nf][0], acc[mf][nf][1]);
                *(float2*)(gp + (size_t)(r + 8) * 128 + c) =
                    make_float2(acc[mf][nf][2], acc[mf][nf][3]);
            }
        }
        __threadfence();                         // partials visible before flag
        __syncthreads();                         // ALL warps' stores fenced
        if (tid == 0) atomicExch(&g_flag[tile], 1);
        return;
    }

    // Second finisher: wait for publish, reset both cells for the next replay.
    if (tid == 0) {
        while (atomicAdd(&g_flag[tile], 0) == 0) { }
        g_flag[tile] = 0;
        g_cnt[tile]  = 0;
    }
    __syncthreads();
    __threadfence();

    float bias[4][2];
    #pragma unroll
    for (int nf = 0; nf < 4; ++nf) {
        bias[nf][0] = bkv[128 + c0 + nf * 8];
        bias[nf][1] = bkv[129 + c0 + nf * 8];
    }

    float* vsm = (float*)smem;
    #pragma unroll
    for (int mf = 0; mf < 2; ++mf) {
        #pragma unroll
        for (int nf = 0; nf < 4; ++nf) {
            int r = r0 + mf * 16;
            int c = c0 + nf * 8;
            float2 p0 = *(const float2*)(gp + (size_t)r * 128 + c);
            float2 p1 = *(const float2*)(gp + (size_t)(r + 8) * 128 + c);
            vsm[r * V_STRIDE + c]           = acc[mf][nf][0] + p0.x + bias[nf][0];
            vsm[r * V_STRIDE + c + 1]       = acc[mf][nf][1] + p0.y + bias[nf][1];
            vsm[(r + 8) * V_STRIDE + c]     = acc[mf][nf][2] + p1.x + bias[nf][0];
            vsm[(r + 8) * V_STRIDE + c + 1] = acc[mf][nf][3] + p1.y + bias[nf][1];
        }
    }
    __syncthreads();

    // Broadcast: each v row written 16x (one per head), coalesced, evict-first.
    float* ob = out + (size_t)tile * MTILE * 2048;
    for (int r = wid; r < MTILE; r += 8) {
        float4 val = *(const float4*)(vsm + r * V_STRIDE + lane * 4);
        float4* orow = (float4*)(ob + (size_t)r * 2048);
        #pragma unroll
        for (int h = 0; h < 16; ++h) __stcs(orow + lane + h * 32, val);
    }
}

// ---------------------------------------------------------------------------
extern "C" void kernel_launch(void* const* d_in, const int* in_sizes, int n_in,
                              void* d_out, int out_size) {
    const float* x   = (const float*)d_in[0];   // (4,4096,2048) fp32
    const float* Wkv = (const float*)d_in[3];   // (256,2048) fp32
    const float* bkv = (const float*)d_in[4];   // (256,) fp32
    float* out = (float*)d_out;                 // (4,4096,2048) fp32

    cudaFuncSetAttribute(mqa_gemm_kernel,
                         cudaFuncAttributeMaxDynamicSharedMemorySize, SMEM_TOTAL);

    convert_w_kernel<<<256, 256>>>(Wkv);
    mqa_gemm_kernel<<<512, 256, SMEM_TOTAL>>>(x, bkv, out);
}

// round 13
// speedup vs baseline: 1.0614x; 1.0614x over previous
#include <cuda_runtime.h>
#include <cuda_fp16.h>
#include <cstdint>

// ============================================================================
// MQA_22436909154690 on GB300 (sm_103 base PTX target -> HMMA mma.sync path).
//
// Math: softmax over singleton axis == 1, so
//   out[b,l] = tile(v[b,l], H),  v = x @ Wv^T + bv,  Wv = Wkv[HD:2HD, :]
// => one GEMM [16384 x 2048] @ [2048 x 128] + bias + broadcast-x16 epilogue.
//
// R13: fully-async loads (fix of R6's broken experiment). x AND B arrive via
// cp.async rings (x: 2 slots fp32, B: 3 slots fp16), one commit group per
// iter, wait_group<1> -> ~1.5 iters of latency slack; NO LDG in the mainloop.
// fp32->fp16 convert uses the own-copy rule: each thread LDS-reads exactly
// the bytes it cp.async'd (legal after wait_group, no barrier), converts,
// STS-writes the double-buffered A tile. ONE __syncthreads per chunk.
// Keeps R10 extras: CTA K-skew, __stcs epilogue, bias preload.
// ============================================================================

static constexpr int KDIM  = 2048;
static constexpr int MTILE = 64;
static constexpr int KC    = 64;
static constexpr int NCH   = KDIM / KC;       // 32 chunks

// SMEM (bytes).
// A fp16: rows 72 halves (144 B)  -> conflict-free ldmatrix/STS.
// X fp32: rows 68 floats (272 B)  -> conflict-free LDS.128.
static constexpr int SA0  = 0;                       // A buf0: [64][72] half
static constexpr int SA1  = 9216;                    // A buf1
static constexpr int SX   = 18432;                   // X ring: 2 x [64][68] fp32
static constexpr int SXSZ = 17408;
static constexpr int SB   = SX + 2 * SXSZ;           // 53248: B ring 3 x [128][72]
static constexpr int SBSZ = 18432;
static constexpr int SMEM_TOTAL = SB + 3 * SBSZ;     // 108544 (x2 = 217 KB/SM)
static constexpr int V_STRIDE = 132;                 // epilogue overlay (33792 B)

// Pre-converted Wv in fp16, chunk-major: [chunk][n=128][k=64]
__device__ __align__(16) __half g_Wh[KDIM * 128];

// ---------------------------------------------------------------------------
__device__ __forceinline__ uint32_t smem_u32(const void* p) {
    uint32_t a;
    asm("{ .reg .u64 t; cvta.to.shared.u64 t, %1; cvt.u32.u64 %0, t; }" : "=r"(a) : "l"(p));
    return a;
}
__device__ __forceinline__ void ldsm4(uint32_t* r, uint32_t addr) {
    asm volatile("ldmatrix.sync.aligned.m8n8.x4.shared.b16 {%0,%1,%2,%3}, [%4];"
                 : "=r"(r[0]), "=r"(r[1]), "=r"(r[2]), "=r"(r[3]) : "r"(addr));
}
__device__ __forceinline__ void hmma(float* d, const uint32_t* a, uint32_t b0, uint32_t b1) {
    asm volatile("mma.sync.aligned.m16n8k16.row.col.f32.f16.f16.f32 "
                 "{%0,%1,%2,%3}, {%4,%5,%6,%7}, {%8,%9}, {%0,%1,%2,%3};"
                 : "+f"(d[0]), "+f"(d[1]), "+f"(d[2]), "+f"(d[3])
                 : "r"(a[0]), "r"(a[1]), "r"(a[2]), "r"(a[3]), "r"(b0), "r"(b1));
}
template <int N>
__device__ __forceinline__ void cpwait() {
    asm volatile("cp.async.wait_group %0;" :: "n"(N) : "memory");
}
__device__ __forceinline__ void cpcommit() {
    asm volatile("cp.async.commit_group;" ::: "memory");
}
__device__ __forceinline__ void cpa16(uint32_t dst, const void* src) {
    asm volatile("cp.async.cg.shared.global [%0], [%1], 16;" :: "r"(dst), "l"(src) : "memory");
}
__device__ __forceinline__ uint32_t h2u(__half2 h) { return *reinterpret_cast<uint32_t*>(&h); }

// ---------------------------------------------------------------------------
// Pre-kernel: Wv = Wkv rows 128..255 -> fp16, chunk-major layout for cp.async.
// ---------------------------------------------------------------------------
__global__ void convert_w_kernel(const float* __restrict__ Wkv) {
    int idx = blockIdx.x * blockDim.x + threadIdx.x;  // 65536 units of 4 halves
    int h4 = idx << 2;
    int c  = h4 >> 13;
    int n  = (h4 >> 6) & 127;
    int k4 = h4 & 63;
    float4 w = *(const float4*)(Wkv + (size_t)(128 + n) * KDIM + c * KC + k4);
    __half2 p0 = __float22half2_rn(make_float2(w.x, w.y));
    __half2 p1 = __float22half2_rn(make_float2(w.z, w.w));
    *(uint2*)(g_Wh + h4) = make_uint2(h2u(p0), h2u(p1));
}

// ---------------------------------------------------------------------------
// 256 CTAs x 256 threads, 2 CTAs/SM. 8 warps as 2(M) x 4(N): 32x32 frags.
// ---------------------------------------------------------------------------
__global__ void __launch_bounds__(256, 2)
mqa_gemm_kernel(const float* __restrict__ x, const float* __restrict__ bkv,
                float* __restrict__ out) {
    extern __shared__ char smem[];
    const uint32_t sb = smem_u32(smem);
    const int tid    = threadIdx.x;
    const int wid    = tid >> 5;
    const int lane   = tid & 31;
    const int warp_m = wid >> 2;
    const int warp_n = wid & 3;
    const int skew   = (blockIdx.x & 1) * (NCH / 2);   // K rotation per CTA parity

    const float* xb = x + (size_t)blockIdx.x * MTILE * KDIM;

    // Bias preload (tiny, L2-hot).
    float bias[4][2];
    {
        int c0 = warp_n * 32 + (lane & 3) * 2;
        #pragma unroll
        for (int nf = 0; nf < 4; ++nf) {
            bias[nf][0] = bkv[128 + c0 + nf * 8];
            bias[nf][1] = bkv[129 + c0 + nf * 8];
        }
    }

    // ldmatrix offsets (within A / B buffers)
    uint32_t aOff[2];
    #pragma unroll
    for (int mf = 0; mf < 2; ++mf)
        aOff[mf] = (uint32_t)(warp_m * 32 + mf * 16 + (lane & 15)) * 144 + ((lane >> 4) << 4);
    uint32_t bOff[2];
    #pragma unroll
    for (int g = 0; g < 2; ++g)
        bOff[g] = (uint32_t)(warp_n * 32 + g * 16 + (lane & 15)) * 144 + ((lane >> 4) << 4);

    float acc[2][4][4];
    #pragma unroll
    for (int mf = 0; mf < 2; ++mf)
        #pragma unroll
        for (int nf = 0; nf < 4; ++nf)
            #pragma unroll
            for (int r = 0; r < 4; ++r) acc[mf][nf][r] = 0.f;

    // --- async issue: ONE commit group = { X[ch] (16KB fp32), B[ch] (16KB) }
    auto issue = [&](int ch, int xslot, int bslot) {
        const uint32_t xbase = sb + SX + xslot * SXSZ;
        #pragma unroll
        for (int j = 0; j < 4; ++j) {
            int u = tid + j * 256;                 // 16B unit: row u>>4, col16 u&15
            cpa16(xbase + (u >> 4) * 272 + ((u & 15) << 4),
                  xb + (size_t)(u >> 4) * KDIM + ch * KC + ((u & 15) << 2));
        }
        const __half* bsrc = g_Wh + (size_t)ch * (128 * KC);
        const uint32_t bbase = sb + SB + bslot * SBSZ;
        #pragma unroll
        for (int j = 0; j < 4; ++j) {
            int u = tid + j * 256;                 // n = u>>3, seg = u&7
            cpa16(bbase + (u >> 3) * 144 + ((u & 7) << 4),
                  bsrc + (u >> 3) * KC + ((u & 7) << 3));
        }
        cpcommit();
    };

    // --- convert own-copied X units -> A fp16 (no barrier needed pre-read)
    auto convert = [&](int xslot, int abuf) {
        const uint32_t xbase = sb + SX + xslot * SXSZ;
        const uint32_t abase = sb + (abuf ? SA1 : SA0);
        #pragma unroll
        for (int j = 0; j < 4; ++j) {
            int u = tid + j * 256;
            float4 f;
            asm volatile("ld.shared.v4.f32 {%0,%1,%2,%3}, [%4];"
                         : "=f"(f.x), "=f"(f.y), "=f"(f.z), "=f"(f.w)
                         : "r"(xbase + (u >> 4) * 272 + ((u & 15) << 4)));
            uint32_t lo = h2u(__float22half2_rn(make_float2(f.x, f.y)));
            uint32_t hi = h2u(__float22half2_rn(make_float2(f.z, f.w)));
            asm volatile("st.shared.v2.u32 [%0], {%1,%2};"
                         :: "r"(abase + (u >> 4) * 144 + ((u & 15) << 3)),
                            "r"(lo), "r"(hi) : "memory");
        }
    };

    auto mmaChunk = [&](int abuf, int bslot) {
        uint32_t bA = sb + (abuf ? SA1 : SA0);
        uint32_t bB = sb + SB + bslot * SBSZ;
        #pragma unroll
        for (int kk = 0; kk < 4; ++kk) {
            uint32_t a[2][4];
            ldsm4(a[0], bA + aOff[0] + kk * 32);
            ldsm4(a[1], bA + aOff[1] + kk * 32);
            uint32_t b[2][4];
            ldsm4(b[0], bB + bOff[0] + kk * 32);
            ldsm4(b[1], bB + bOff[1] + kk * 32);
            #pragma unroll
            for (int mf = 0; mf < 2; ++mf) {
                hmma(acc[mf][0], a[mf], b[0][0], b[0][2]);
                hmma(acc[mf][1], a[mf], b[0][1], b[0][3]);
                hmma(acc[mf][2], a[mf], b[1][0], b[1][2]);
                hmma(acc[mf][3], a[mf], b[1][1], b[1][3]);
            }
        }
    };

    // --- prologue: groups {0},{1} in flight; convert chunk 0; publish ---
    issue((0 + skew) & 31, 0, 0);
    issue((1 + skew) & 31, 1, 1);
    cpwait<1>();                 // group 0 landed (own copies)
    convert(0, 0);               // A[0] from own X[0] bytes
    __syncthreads();             // publish A[0], B[0]

    // --- main loop: ONE barrier per chunk, zero LDG ---
    for (int it = 0; it < NCH; ++it) {
        // entering: A[it&1], B[it%3] published; group(it+1) maybe in flight
        if (it + 2 < NCH)
            issue((it + 2 + skew) & 31, it & 1, (it + 2) % 3);  // X slot it&1 free
        mmaChunk(it & 1, it % 3);
        if (it + 1 < NCH) {
            if (it + 2 < NCH) cpwait<1>();   // group(it+1) landed, (it+2) in flight
            else              cpwait<0>();
            convert((it + 1) & 1, (it + 1) & 1);
        }
        __syncthreads();                      // publish A[it+1], B[it+1]
    }

    // --- epilogue ---
    float* vsm = (float*)smem;
    {
        int r0 = warp_m * 32 + (lane >> 2);
        #pragma unroll
        for (int mf = 0; mf < 2; ++mf) {
            #pragma unroll
            for (int nf = 0; nf < 4; ++nf) {
                int r = r0 + mf * 16;
                int c = warp_n * 32 + nf * 8 + (lane & 3) * 2;
                vsm[r * V_STRIDE + c]           = acc[mf][nf][0] + bias[nf][0];
                vsm[r * V_STRIDE + c + 1]       = acc[mf][nf][1] + bias[nf][1];
                vsm[(r + 8) * V_STRIDE + c]     = acc[mf][nf][2] + bias[nf][0];
                vsm[(r + 8) * V_STRIDE + c + 1] = acc[mf][nf][3] + bias[nf][1];
            }
        }
    }
    __syncthreads();

    // Broadcast: each v row written 16x (one per head), coalesced, evict-first.
    float* ob = out + (size_t)blockIdx.x * MTILE * 2048;
    for (int r = wid; r < MTILE; r += 8) {
        float4 val = *(const float4*)(vsm + r * V_STRIDE + lane * 4);
        float4* orow = (float4*)(ob + (size_t)r * 2048);
        #pragma unroll
        for (int h = 0; h < 16; ++h) __stcs(orow + lane + h * 32, val);
    }
}

// ---------------------------------------------------------------------------
extern "C" void kernel_launch(void* const* d_in, const int* in_sizes, int n_in,
                              void* d_out, int out_size) {
    const float* x   = (const float*)d_in[0];   // (4,4096,2048) fp32
    const float* Wkv = (const float*)d_in[3];   // (256,2048) fp32
    const float* bkv = (const float*)d_in[4];   // (256,) fp32
    float* out = (float*)d_out;                 // (4,4096,2048) fp32

    cudaFuncSetAttribute(mqa_gemm_kernel,
                         cudaFuncAttributeMaxDynamicSharedMemorySize, SMEM_TOTAL);

    convert_w_kernel<<<256, 256>>>(Wkv);
    mqa_gemm_kernel<<<16384 / MTILE, 256, SMEM_TOTAL>>>(x, bkv, out);
}

// round 14
// speedup vs baseline: 1.1926x; 1.1236x over previous
#include <cuda_runtime.h>
#include <cuda_fp16.h>
#include <cstdint>

// ============================================================================
// MQA_22436909154690 on GB300 (sm_103 base PTX target -> HMMA mma.sync path).
//
// Math: softmax over singleton axis == 1, so
//   out[b,l] = tile(v[b,l], H),  v = x @ Wv^T + bv,  Wv = Wkv[HD:2HD, :]
// => one GEMM [16384 x 2048] @ [2048 x 128] + bias + broadcast-x16 epilogue.
//
// R14 = R10 + K-SPLIT WARP GRID. Model (validated by R6/R8/R10/R13 deltas):
// the mainloop is L1-data-bound at ~104 KB/CTA-chunk; A-LDSM is 32 KB of it
// due to 4x duplication across warp_n. New warp grid 2(M) x 2(N) x 2(K):
// each warp = 32x64 output tile, half the k-range -> A dup 4x->2x,
// total ~88 KB/chunk (-15%). k-half partials summed in a 2-phase epilogue.
// ============================================================================

static constexpr int KDIM  = 2048;
static constexpr int MTILE = 64;
static constexpr int KC    = 64;
static constexpr int NCH   = KDIM / KC;       // 32 chunks

// SMEM (bytes). 72 halves/row padding -> conflict-free ldmatrix.
static constexpr int SA0 = 0;                        // A buf0: [64][72] half
static constexpr int SA1 = 9216;                     // A buf1
static constexpr int SB  = 18432;                    // B bufs: 3 x [128][72] half
static constexpr int SBSZ = 18432;
static constexpr int SMEM_TOTAL = SB + 3 * SBSZ;     // 73728 -> 2 CTAs/SM
static constexpr int V_STRIDE  = 132;                // epilogue overlay (33792 B)

// Pre-converted Wv in fp16, chunk-major: [chunk][n=128][k=64]
__device__ __align__(16) __half g_Wh[KDIM * 128];

// ---------------------------------------------------------------------------
__device__ __forceinline__ uint32_t smem_u32(const void* p) {
    uint32_t a;
    asm("{ .reg .u64 t; cvta.to.shared.u64 t, %1; cvt.u32.u64 %0, t; }" : "=r"(a) : "l"(p));
    return a;
}
__device__ __forceinline__ void ldsm4(uint32_t* r, uint32_t addr) {
    asm volatile("ldmatrix.sync.aligned.m8n8.x4.shared.b16 {%0,%1,%2,%3}, [%4];"
                 : "=r"(r[0]), "=r"(r[1]), "=r"(r[2]), "=r"(r[3]) : "r"(addr));
}
__device__ __forceinline__ void hmma(float* d, const uint32_t* a, uint32_t b0, uint32_t b1) {
    asm volatile("mma.sync.aligned.m16n8k16.row.col.f32.f16.f16.f32 "
                 "{%0,%1,%2,%3}, {%4,%5,%6,%7}, {%8,%9}, {%0,%1,%2,%3};"
                 : "+f"(d[0]), "+f"(d[1]), "+f"(d[2]), "+f"(d[3])
                 : "r"(a[0]), "r"(a[1]), "r"(a[2]), "r"(a[3]), "r"(b0), "r"(b1));
}
template <int N>
__device__ __forceinline__ void cpwait() {
    asm volatile("cp.async.wait_group %0;" :: "n"(N) : "memory");
}
__device__ __forceinline__ void cpcommit() {
    asm volatile("cp.async.commit_group;" ::: "memory");
}
__device__ __forceinline__ void cpa16(uint32_t dst, const void* src) {
    asm volatile("cp.async.cg.shared.global [%0], [%1], 16;" :: "r"(dst), "l"(src) : "memory");
}
__device__ __forceinline__ uint32_t h2u(__half2 h) { return *reinterpret_cast<uint32_t*>(&h); }

// ---------------------------------------------------------------------------
// Pre-kernel: Wv = Wkv rows 128..255 -> fp16, chunk-major layout for cp.async.
// ---------------------------------------------------------------------------
__global__ void convert_w_kernel(const float* __restrict__ Wkv) {
    int idx = blockIdx.x * blockDim.x + threadIdx.x;  // 65536 units of 4 halves
    int h4 = idx << 2;
    int c  = h4 >> 13;
    int n  = (h4 >> 6) & 127;
    int k4 = h4 & 63;
    float4 w = *(const float4*)(Wkv + (size_t)(128 + n) * KDIM + c * KC + k4);
    __half2 p0 = __float22half2_rn(make_float2(w.x, w.y));
    __half2 p1 = __float22half2_rn(make_float2(w.z, w.w));
    *(uint2*)(g_Wh + h4) = make_uint2(h2u(p0), h2u(p1));
}

// ---------------------------------------------------------------------------
// 256 CTAs x 256 threads, 2 CTAs/SM.
// Warp grid 2(M) x 2(N) x 2(K): wid -> warp_k = wid>>2, warp_m = (wid>>1)&1,
// warp_n = wid&1. Each warp: 32x64 tile, k-half warp_k within each chunk.
// ---------------------------------------------------------------------------
__global__ void __launch_bounds__(256, 2)
mqa_gemm_kernel(const float* __restrict__ x, const float* __restrict__ bkv,
                float* __restrict__ out) {
    extern __shared__ char smem[];
    const uint32_t sb = smem_u32(smem);
    const int tid    = threadIdx.x;
    const int wid    = tid >> 5;
    const int lane   = tid & 31;
    const int warp_k = wid >> 2;
    const int warp_m = (wid >> 1) & 1;
    const int warp_n = wid & 1;
    const int skew   = (blockIdx.x & 1) * (NCH / 2);

    const float* xb = x + (size_t)blockIdx.x * MTILE * KDIM;

    // ldmatrix offsets. kbyte: this warp's k-half start within a 144 B row.
    const uint32_t kbyte = (uint32_t)warp_k * 64;
    uint32_t aOff[2];
    #pragma unroll
    for (int mf = 0; mf < 2; ++mf)
        aOff[mf] = (uint32_t)(warp_m * 32 + mf * 16 + (lane & 15)) * 144
                 + ((lane >> 4) << 4) + kbyte;
    uint32_t bOff[4];
    #pragma unroll
    for (int g = 0; g < 4; ++g)
        bOff[g] = (uint32_t)(warp_n * 64 + g * 16 + (lane & 15)) * 144
                + ((lane >> 4) << 4) + kbyte;

    float acc[2][8][4];                     // 32x64 tile: 64 fp32 regs
    #pragma unroll
    for (int mf = 0; mf < 2; ++mf)
        #pragma unroll
        for (int nf = 0; nf < 8; ++nf)
            #pragma unroll
            for (int r = 0; r < 4; ++r) acc[mf][nf][r] = 0.f;

    float4 xs[2][2];
    const int f8a = tid;
    const int f8b = tid + 256;

    auto ldx = [&](int ch) {
        const float* p0 = xb + (size_t)(f8a >> 3) * KDIM + ch * KC + ((f8a & 7) << 3);
        const float* p1 = xb + (size_t)(f8b >> 3) * KDIM + ch * KC + ((f8b & 7) << 3);
        xs[0][0] = __ldcs((const float4*)p0);
        xs[0][1] = __ldcs((const float4*)p0 + 1);
        xs[1][0] = __ldcs((const float4*)p1);
        xs[1][1] = __ldcs((const float4*)p1 + 1);
    };
    auto stx = [&](int buf) {
        uint32_t base = (buf ? SA1 : SA0);
        #pragma unroll
        for (int i = 0; i < 2; ++i) {
            int f8 = (i ? f8b : f8a);
            __half2 h0 = __float22half2_rn(make_float2(xs[i][0].x, xs[i][0].y));
            __half2 h1 = __float22half2_rn(make_float2(xs[i][0].z, xs[i][0].w));
            __half2 h2 = __float22half2_rn(make_float2(xs[i][1].x, xs[i][1].y));
            __half2 h3 = __float22half2_rn(make_float2(xs[i][1].z, xs[i][1].w));
            uint4 v = make_uint4(h2u(h0), h2u(h1), h2u(h2), h2u(h3));
            *(uint4*)(smem + base + (((f8 >> 3) * 72 + ((f8 & 7) << 3)) << 1)) = v;
        }
    };
    auto cpB = [&](int ch, int buf) {
        const __half* src = g_Wh + (size_t)ch * (128 * KC);
        uint32_t dbase = sb + SB + buf * SBSZ;
        #pragma unroll
        for (int j = 0; j < 4; ++j) {
            int idx = tid + j * 256;
            int n = idx >> 3, seg = idx & 7;
            cpa16(dbase + ((n * 72 + seg * 8) << 1), src + n * KC + seg * 8);
        }
        cpcommit();
    };
    auto mmaChunk = [&](int abuf, int bbuf) {
        uint32_t bA = sb + (abuf ? SA1 : SA0);
        uint32_t bB = sb + SB + bbuf * SBSZ;
        #pragma unroll
        for (int kk = 0; kk < 2; ++kk) {            // 2 k16 steps in this k-half
            uint32_t a[2][4];
            ldsm4(a[0], bA + aOff[0] + kk * 32);
            ldsm4(a[1], bA + aOff[1] + kk * 32);
            #pragma unroll
            for (int g = 0; g < 4; ++g) {           // 4 B groups of 16 cols
                uint32_t b[4];
                ldsm4(b, bB + bOff[g] + kk * 32);
                #pragma unroll
                for (int mf = 0; mf < 2; ++mf) {
                    hmma(acc[mf][2 * g],     a[mf], b[0], b[2]);
                    hmma(acc[mf][2 * g + 1], a[mf], b[1], b[3]);
                }
            }
        }
    };

    // --- prologue ---
    cpB(skew, 0);
    cpB(skew + 1, 1);
    ldx(skew);
    stx(0);
    ldx(skew + 1);
    cpwait<1>();
    __syncthreads();

    // --- main loop: ONE barrier per chunk (R10 structure) ---
    for (int it = 0; it < NCH; ++it) {
        if (it + 1 < NCH) stx((it + 1) & 1);
        if (it + 2 < NCH) {
            ldx((it + 2 + skew) & 31);
            cpB((it + 2 + skew) & 31, (it + 2) % 3);
        }
        mmaChunk(it & 1, it % 3);
        if (it + 2 < NCH) cpwait<1>();
        else              cpwait<0>();
        __syncthreads();
    }

    // --- epilogue: 2-phase k-half reduction, then broadcast ---
    const int r0 = warp_m * 32 + (lane >> 2);
    const int c0 = warp_n * 64 + (lane & 3) * 2;
    float* vsm = (float*)smem;
    __syncthreads();

    if (warp_k == 0) {
        #pragma unroll
        for (int mf = 0; mf < 2; ++mf) {
            #pragma unroll
            for (int nf = 0; nf < 8; ++nf) {
                int r = r0 + mf * 16;
                int c = c0 + nf * 8;
                vsm[r * V_STRIDE + c]           = acc[mf][nf][0];
                vsm[r * V_STRIDE + c + 1]       = acc[mf][nf][1];
                vsm[(r + 8) * V_STRIDE + c]     = acc[mf][nf][2];
                vsm[(r + 8) * V_STRIDE + c + 1] = acc[mf][nf][3];
            }
        }
    }
    __syncthreads();
    if (warp_k == 1) {
        #pragma unroll
        for (int mf = 0; mf < 2; ++mf) {
            #pragma unroll
            for (int nf = 0; nf < 8; ++nf) {
                int r = r0 + mf * 16;
                int c = c0 + nf * 8;
                float b0 = bkv[128 + c];
                float b1 = bkv[129 + c];
                vsm[r * V_STRIDE + c]           += acc[mf][nf][0] + b0;
                vsm[r * V_STRIDE + c + 1]       += acc[mf][nf][1] + b1;
                vsm[(r + 8) * V_STRIDE + c]     += acc[mf][nf][2] + b0;
                vsm[(r + 8) * V_STRIDE + c + 1] += acc[mf][nf][3] + b1;
            }
        }
    }
    __syncthreads();

    // Broadcast: each v row written 16x (one per head), coalesced, evict-first.
    float* ob = out + (size_t)blockIdx.x * MTILE * 2048;
    for (int r = wid; r < MTILE; r += 8) {
        float4 val = *(const float4*)(vsm + r * V_STRIDE + lane * 4);
        float4* orow = (float4*)(ob + (size_t)r * 2048);
        #pragma unroll
        for (int h = 0; h < 16; ++h) __stcs(orow + lane + h * 32, val);
    }
}

// ---------------------------------------------------------------------------
extern "C" void kernel_launch(void* const* d_in, const int* in_sizes, int n_in,
                              void* d_out, int out_size) {
    const float* x   = (const float*)d_in[0];   // (4,4096,2048) fp32
    const float* Wkv = (const float*)d_in[3];   // (256,2048) fp32
    const float* bkv = (const float*)d_in[4];   // (256,) fp32
    float* out = (float*)d_out;                 // (4,4096,2048) fp32

    cudaFuncSetAttribute(mqa_gemm_kernel,
                         cudaFuncAttributeMaxDynamicSharedMemorySize, SMEM_TOTAL);

    convert_w_kernel<<<256, 256>>>(Wkv);
    mqa_gemm_kernel<<<16384 / MTILE, 256, SMEM_TOTAL>>>(x, bkv, out);
}